// round 3
// baseline (speedup 1.0000x reference)
#include <cuda_runtime.h>
#include <cuda_bf16.h>
#include <math.h>
#include <stdint.h>

typedef unsigned long long ull;

// ---------------- scratch (device globals; no allocation allowed) ----------
__device__ float g_FH[8 * 256 * 1024];   // conv+bn+relu out, flat == feat_high [b][m][c]
__device__ float g_Q [8 * 4096 * 64];    // mid_low  [n][d]  (n flat over batches)
__device__ float g_Kt[8 * 64 * 1024];    // mid_high transposed [b][d][m]

// ---------------- f32x2 helpers --------------------------------------------
__device__ __forceinline__ void fma2(ull &d, ull a, ull b) {
    asm("fma.rn.f32x2 %0, %1, %2, %0;" : "+l"(d) : "l"(a), "l"(b));
}
__device__ __forceinline__ ull mul2(ull a, ull b) {
    ull r; asm("mul.rn.f32x2 %0, %1, %2;" : "=l"(r) : "l"(a), "l"(b)); return r;
}
__device__ __forceinline__ ull pk2(float x) {
    ull r; asm("mov.b64 %0, {%1, %1};" : "=l"(r) : "r"(__float_as_uint(x))); return r;
}
__device__ __forceinline__ float2 upk(ull v) {
    float2 f; asm("mov.b64 {%0, %1}, %2;" : "=f"(f.x), "=f"(f.y) : "l"(v)); return f;
}

// ---------------- cp.async helpers -----------------------------------------
__device__ __forceinline__ uint32_t cvta_s(const void* p) {
    return (uint32_t)__cvta_generic_to_shared(p);
}
__device__ __forceinline__ void cp16(uint32_t dst, const void* src) {
    asm volatile("cp.async.cg.shared.global [%0], [%1], 16;\n" :: "r"(dst), "l"(src) : "memory");
}
__device__ __forceinline__ void cp_commit() {
    asm volatile("cp.async.commit_group;\n" ::: "memory");
}

// ============================================================================
// Kernel A: 1x1 conv + BN + ReLU.  x[b][o][s] = relu(bn(sum_c FHin[b][c][s]*W[o][c]))
// grid (s_tiles=8, o_tiles=4, b=8), 256 threads. Tile 64o x 128s, k-chunks of 64.
// ============================================================================
__global__ void __launch_bounds__(256) conv_k(
    const float* __restrict__ FHin, const float* __restrict__ Wc,
    const float* __restrict__ gam, const float* __restrict__ bet,
    const float* __restrict__ mu,  const float* __restrict__ var)
{
    __shared__ float Ws[64 * 64];
    __shared__ float Xs[64 * 128];
    const int t = threadIdx.x, tx = t & 31, ty = t >> 5;
    const int st = blockIdx.x, ot = blockIdx.y, b = blockIdx.z;
    const float* Xg = FHin + (size_t)b * 512 * 1024 + st * 128;
    const float* Wg = Wc + (size_t)ot * 64 * 512;

    ull acc[8][2];
    #pragma unroll
    for (int r = 0; r < 8; r++) { acc[r][0] = 0ull; acc[r][1] = 0ull; }

    for (int kc = 0; kc < 8; kc++) {
        __syncthreads();
        #pragma unroll
        for (int i = 0; i < 16; i++) {
            int id = i * 256 + t; int row = id >> 6, col = id & 63;
            Ws[row * 64 + col] = Wg[(size_t)row * 512 + kc * 64 + col];
        }
        #pragma unroll
        for (int i = 0; i < 8; i++) {
            int id = i * 256 + t; int row = id >> 5, c4 = id & 31;
            *(float4*)&Xs[row * 128 + c4 * 4] =
                *(const float4*)(Xg + (size_t)(kc * 64 + row) * 1024 + c4 * 4);
        }
        __syncthreads();
        #pragma unroll 8
        for (int k = 0; k < 64; k++) {
            ull x0 = *(const ull*)&Xs[k * 128 + tx * 4];
            ull x1 = *(const ull*)&Xs[k * 128 + tx * 4 + 2];
            #pragma unroll
            for (int r = 0; r < 8; r++) {
                ull wv = pk2(Ws[(ty * 8 + r) * 64 + k]);
                fma2(acc[r][0], wv, x0);
                fma2(acc[r][1], wv, x1);
            }
        }
    }
    #pragma unroll
    for (int r = 0; r < 8; r++) {
        int o = ot * 64 + ty * 8 + r;
        float inv = gam[o] * rsqrtf(var[o] + 1e-5f);
        float bs  = bet[o] - mu[o] * inv;
        float2 a = upk(acc[r][0]), c2 = upk(acc[r][1]);
        float4 v;
        v.x = fmaxf(fmaf(a.x,  inv, bs), 0.f);
        v.y = fmaxf(fmaf(a.y,  inv, bs), 0.f);
        v.z = fmaxf(fmaf(c2.x, inv, bs), 0.f);
        v.w = fmaxf(fmaf(c2.y, inv, bs), 0.f);
        *(float4*)&g_FH[((size_t)b * 256 + o) * 1024 + st * 128 + tx * 4] = v;
    }
}

// ============================================================================
// Kernel B/C: fc GEMM. out[n][d] = sum_c X[n][c]*W[d][c] + bias[d].
// rows flat; tile 128n x 64d, 256 threads, thread 8n x 4d. TRANSC=1 reads g_FH
// and writes g_Kt[b][d][m] transposed; else writes g_Q[n][d].
// ============================================================================
template<bool TRANSC>
__global__ void __launch_bounds__(256) fc_k(
    const float* __restrict__ Xin, const float* __restrict__ W,
    const float* __restrict__ bias)
{
    __shared__ float Xs[128 * 64];
    __shared__ float Ws[64 * 66];   // transposed [c][d], pad 66
    const int t = threadIdx.x, tx = t & 15, ty = t >> 4;
    const int n0 = blockIdx.x * 128;
    const float* X = TRANSC ? (const float*)g_FH : Xin;

    ull acc[8][2];
    #pragma unroll
    for (int r = 0; r < 8; r++) { acc[r][0] = 0ull; acc[r][1] = 0ull; }

    for (int kc = 0; kc < 4; kc++) {
        __syncthreads();
        #pragma unroll
        for (int i = 0; i < 8; i++) {
            int id = i * 256 + t; int row = id >> 4, c4 = id & 15;
            *(float4*)&Xs[row * 64 + c4 * 4] =
                *(const float4*)(X + (size_t)(n0 + row) * 256 + kc * 64 + c4 * 4);
        }
        #pragma unroll
        for (int i = 0; i < 16; i++) {
            int id = i * 256 + t; int d = id >> 6, c = id & 63;
            Ws[c * 66 + d] = W[(size_t)d * 256 + kc * 64 + c];
        }
        __syncthreads();
        #pragma unroll 8
        for (int c = 0; c < 64; c++) {
            ull w0 = *(const ull*)&Ws[c * 66 + tx * 4];
            ull w1 = *(const ull*)&Ws[c * 66 + tx * 4 + 2];
            #pragma unroll
            for (int r = 0; r < 8; r++) {
                ull xv = pk2(Xs[(ty * 8 + r) * 64 + c]);
                fma2(acc[r][0], xv, w0);
                fma2(acc[r][1], xv, w1);
            }
        }
    }
    if (!TRANSC) {
        float4 bv = *(const float4*)(bias + tx * 4);
        #pragma unroll
        for (int r = 0; r < 8; r++) {
            float2 a = upk(acc[r][0]), c2 = upk(acc[r][1]);
            float4 v = make_float4(a.x + bv.x, a.y + bv.y, c2.x + bv.z, c2.y + bv.w);
            *(float4*)&g_Q[(size_t)(n0 + ty * 8 + r) * 64 + tx * 4] = v;
        }
    } else {
        float4 bv = *(const float4*)(bias + tx * 4);
        #pragma unroll
        for (int r = 0; r < 8; r++) {
            int n = n0 + ty * 8 + r;
            int bb = n >> 10, m = n & 1023;
            float2 a = upk(acc[r][0]), c2 = upk(acc[r][1]);
            g_Kt[((size_t)bb * 64 + tx * 4 + 0) * 1024 + m] = a.x  + bv.x;
            g_Kt[((size_t)bb * 64 + tx * 4 + 1) * 1024 + m] = a.y  + bv.y;
            g_Kt[((size_t)bb * 64 + tx * 4 + 2) * 1024 + m] = c2.x + bv.z;
            g_Kt[((size_t)bb * 64 + tx * 4 + 3) * 1024 + m] = c2.y + bv.w;
        }
    }
}

// ============================================================================
// Kernel D: fused attention. Per block: 64 Q-rows of one batch.
// S = Q·K^T (f32x2), online softmax (warp-exclusive rows), O += P·FH (f32x2),
// cp.async double-buffered Kt/FH tiles, transposed coalesced epilogue.
// smem: Q 4096 | Kt 2x4096 | FH 2x(64x260) | P 4096  = 49664 fl = 194KB
// ============================================================================
#define FH_STRIDE 260
#define FH_BUF    16640           // floats per FH buffer
#define KT_BUF    4096

__device__ __forceinline__ void issue_tile(int t, int mt, int buf,
    uint32_t Ktsa, uint32_t FHsa, const float* Ktg, const float* FHg)
{
    const float* ks = Ktg + mt * 64;
    #pragma unroll
    for (int i = 0; i < 2; i++) {
        int id = i * 512 + t; int d = id >> 4, ch = id & 15;
        cp16(Ktsa + (uint32_t)(buf * KT_BUF + d * 64 + ch * 4) * 4,
             ks + (size_t)d * 1024 + ch * 4);
    }
    const float* fs = FHg + (size_t)mt * 64 * 256;
    #pragma unroll
    for (int i = 0; i < 8; i++) {
        int id = i * 512 + t; int row = id >> 6, ch = id & 63;
        cp16(FHsa + (uint32_t)(buf * FH_BUF + row * FH_STRIDE + ch * 4) * 4,
             fs + (size_t)row * 256 + ch * 4);
    }
}

__global__ void __launch_bounds__(512, 1) attn_k(
    const float* __restrict__ scp, float* __restrict__ out)
{
    extern __shared__ float sm[];
    float* Q_s  = sm;                 // 4096
    float* Kt_s = sm + 4096;          // 2 x 4096
    float* FH_s = sm + 12288;         // 2 x 16640
    float* P_s  = sm + 45568;         // 4096

    const int b = blockIdx.y, nblk = blockIdx.x;
    const int t = threadIdx.x, w = t >> 5, l = t & 31;

    const float* Qg  = g_Q  + ((size_t)b * 4096 + nblk * 64) * 64;
    const float* Ktg = g_Kt + (size_t)b * 64 * 1024;
    const float* FHg = g_FH + (size_t)b * 1024 * 256;

    uint32_t Qsa  = cvta_s(Q_s);
    uint32_t Ktsa = cvta_s(Kt_s);
    uint32_t FHsa = cvta_s(FH_s);

    // prologue: group G0 = {Q tile, tile 0}
    #pragma unroll
    for (int i = 0; i < 2; i++) {
        int id = i * 512 + t;
        cp16(Qsa + (uint32_t)id * 16, Qg + id * 4);
    }
    issue_tile(t, 0, 0, Ktsa, FHsa, Ktg, FHg);
    cp_commit();

    ull oacc[4][4];
    #pragma unroll
    for (int r = 0; r < 4; r++)
        #pragma unroll
        for (int k = 0; k < 4; k++) oacc[r][k] = 0ull;
    float mrun[4] = {-INFINITY, -INFINITY, -INFINITY, -INFINITY};
    float lrun[4] = {0.f, 0.f, 0.f, 0.f};

    for (int tb = 0; tb < 16; tb++) {
        if (tb < 15) {
            issue_tile(t, tb + 1, (tb + 1) & 1, Ktsa, FHsa, Ktg, FHg);
            cp_commit();
            asm volatile("cp.async.wait_group 1;\n" ::: "memory");
        } else {
            asm volatile("cp.async.wait_group 0;\n" ::: "memory");
        }
        __syncthreads();

        const float* KtB = Kt_s + (tb & 1) * KT_BUF;
        const float* FHB = FH_s + (tb & 1) * FH_BUF;
        const float* Qw  = Q_s + (w * 4) * 64;

        // ---- S = Q . K^T : thread -> rows w*4..+3, cols {2l, 2l+1} ----
        ull sacc[4] = {0ull, 0ull, 0ull, 0ull};
        #pragma unroll 8
        for (int d = 0; d < 64; d++) {
            ull kt = *(const ull*)(KtB + d * 64 + 2 * l);
            #pragma unroll
            for (int r = 0; r < 4; r++)
                fma2(sacc[r], pk2(Qw[r * 64 + d]), kt);
        }

        // ---- online softmax (rows are warp-exclusive) ----
        #pragma unroll
        for (int r = 0; r < 4; r++) {
            float2 sv = upk(sacc[r]);
            float mt_ = fmaxf(sv.x, sv.y);
            #pragma unroll
            for (int off = 16; off; off >>= 1)
                mt_ = fmaxf(mt_, __shfl_xor_sync(0xffffffffu, mt_, off));
            float mnew  = fmaxf(mrun[r], mt_);
            float alpha = __expf(mrun[r] - mnew);
            float px = __expf(sv.x - mnew);
            float py = __expf(sv.y - mnew);
            float ps = px + py;
            #pragma unroll
            for (int off = 16; off; off >>= 1)
                ps += __shfl_xor_sync(0xffffffffu, ps, off);
            lrun[r] = lrun[r] * alpha + ps;
            mrun[r] = mnew;
            ull a2 = pk2(alpha);
            #pragma unroll
            for (int k = 0; k < 4; k++) oacc[r][k] = mul2(oacc[r][k], a2);
            *(float2*)(P_s + (w * 4 + r) * 64 + 2 * l) = make_float2(px, py);
        }
        __syncwarp();

        // ---- O += P . FH : thread -> rows w*4..+3, cols l*8..l*8+7 ----
        const float* Pw = P_s + (w * 4) * 64;
        #pragma unroll 8
        for (int m = 0; m < 64; m++) {
            const float* fr = FHB + m * FH_STRIDE + l * 8;
            ull f0 = *(const ull*)(fr + 0);
            ull f1 = *(const ull*)(fr + 2);
            ull f2 = *(const ull*)(fr + 4);
            ull f3 = *(const ull*)(fr + 6);
            #pragma unroll
            for (int r = 0; r < 4; r++) {
                ull pv = pk2(Pw[r * 64 + m]);
                fma2(oacc[r][0], pv, f0);
                fma2(oacc[r][1], pv, f1);
                fma2(oacc[r][2], pv, f2);
                fma2(oacc[r][3], pv, f3);
            }
        }
        __syncthreads();
    }

    // ---- epilogue: O[n][c] * scale / l  -> out[b][c][n] via smem transpose ----
    float sc = scp[0];
    float* O_s = FH_s;                        // reuse, stride 257
    #pragma unroll
    for (int r = 0; r < 4; r++) {
        float inv = sc / lrun[r];
        int row = w * 4 + r;
        #pragma unroll
        for (int k = 0; k < 4; k++) {
            float2 v = upk(oacc[r][k]);
            O_s[row * 257 + l * 8 + 2 * k + 0] = v.x * inv;
            O_s[row * 257 + l * 8 + 2 * k + 1] = v.y * inv;
        }
    }
    __syncthreads();
    float* outB = out + (size_t)b * 256 * 4096 + nblk * 64;
    #pragma unroll
    for (int j = 0; j < 8; j++) {
        int c  = j * 32 + (t >> 4);
        int nn = (t & 15) * 4;
        float4 v;
        v.x = O_s[(nn + 0) * 257 + c];
        v.y = O_s[(nn + 1) * 257 + c];
        v.z = O_s[(nn + 2) * 257 + c];
        v.w = O_s[(nn + 3) * 257 + c];
        *(float4*)(outB + (size_t)c * 4096 + nn) = v;
    }
}

// ============================================================================
extern "C" void kernel_launch(void* const* d_in, const int* in_sizes, int n_in,
                              void* d_out, int out_size)
{
    const float* fms_low  = (const float*)d_in[0];
    const float* fms_high = (const float*)d_in[1];
    const float* w_conv   = (const float*)d_in[2];
    const float* gam      = (const float*)d_in[3];
    const float* bet      = (const float*)d_in[4];
    const float* mu       = (const float*)d_in[5];
    const float* var      = (const float*)d_in[6];
    const float* fc1w     = (const float*)d_in[7];
    const float* fc1b     = (const float*)d_in[8];
    const float* fc2w     = (const float*)d_in[9];
    const float* fc2b     = (const float*)d_in[10];
    const float* scale    = (const float*)d_in[11];
    float* out = (float*)d_out;

    conv_k<<<dim3(8, 4, 8), 256>>>(fms_high, w_conv, gam, bet, mu, var);
    fc_k<false><<<256, 256>>>(fms_low, fc1w, fc1b);
    fc_k<true ><<<64,  256>>>(nullptr,  fc2w, fc2b);

    cudaFuncSetAttribute(attn_k, cudaFuncAttributeMaxDynamicSharedMemorySize, 198656);
    attn_k<<<dim3(64, 8), 512, 198656>>>(scale, out);
}